// round 14
// baseline (speedup 1.0000x reference)
#include <cuda_runtime.h>
#include <cuda_fp16.h>
#include <math.h>
#include <stdint.h>

#define B_SZ   4
#define L_SEQ  2048
#define DMODEL 1024
#define DINNER 2048
#define DSTATE 16
#define MTOT   (B_SZ * L_SEQ)   // 8192

// ---------------- scratch ----------------------------------------------------
__device__ __half g_xt_h  [(size_t)MTOT * DMODEL];      // x^T as fp16
__device__ __half g_xz_h  [(size_t)MTOT * 2 * DINNER];  // in_proj out (u|z) fp16
__device__ __half g_uact_h[(size_t)MTOT * DINNER];      // conv+silu, fp16
__device__ __half g_xdbl_h[(size_t)MTOT * 96];          // x_proj out, fp16
__device__ float  g_part  [(size_t)4 * MTOT * 96];      // split-K partials
__device__ float  g_delta [(size_t)MTOT * DINNER];      // softplus(dt)
__device__ __half g_yv_h  [(size_t)MTOT * DINNER];      // scan out, fp16
__device__ float  g_o2    [(size_t)MTOT * DMODEL];
__device__ __half g_wr_h  [7667712];                    // all weights, fp16
__device__ __half g_woutT [(size_t)DINNER * DMODEL];    // w_out^T  [d][m]
__device__ __half g_wc    [(size_t)DMODEL * DINNER];    // w_p@w_out [e][d]

#define WOFF_IN  0
#define WOFF_X   4194304
#define WOFF_DT  4390912
#define WOFF_OUT 4521984
#define WOFF_P   6619136

__device__ __forceinline__ void cp16(uint32_t dst, const void* src, bool pred) {
    int sz = pred ? 16 : 0;
    asm volatile("cp.async.cg.shared.global [%0], [%1], 16, %2;\n"
                 :: "r"(dst), "l"(src), "r"(sz));
}

__device__ __forceinline__ void ldsm4(uint32_t* r, uint32_t addr) {
    asm volatile("ldmatrix.sync.aligned.m8n8.x4.shared.b16 {%0,%1,%2,%3}, [%4];"
                 : "=r"(r[0]), "=r"(r[1]), "=r"(r[2]), "=r"(r[3]) : "r"(addr));
}

#define MMA_F16(c, a0, a1, a2, a3, b0, b1)                            \
    asm volatile(                                                     \
        "mma.sync.aligned.m16n8k16.row.col.f32.f16.f16.f32 "          \
        "{%0,%1,%2,%3}, {%4,%5,%6,%7}, {%8,%9}, {%0,%1,%2,%3};\n"     \
        : "+f"(c[0]), "+f"(c[1]), "+f"(c[2]), "+f"(c[3])              \
        : "r"(a0), "r"(a1), "r"(a2), "r"(a3), "r"(b0), "r"(b1))

// ---------------- fp16 GEMM (fp32 accum), 64-k chunks, 3 stages --------------
// A half [M, lda]; W half [N, ldb]; C[m,n] = sum_k A[m,k] W[n,k] (+bias)(+act).
// ACT: 0 none, 1 +bias, 2 +bias+softplus.  OUTH: write half (else float).
template<int ACT, bool NGUARD, bool OUTH>
__global__ void __launch_bounds__(256, 2)
hgemm(const __half* __restrict__ A, const __half* __restrict__ W,
      const float* __restrict__ bias, void* __restrict__ Cv,
      int K, int lda, int ldb, int ldc, int Nt, long cz)
{
    extern __shared__ float sm[];
    const int tid  = threadIdx.x;
    const int wid  = tid >> 5, lane = tid & 31;
    const int m0   = blockIdx.y * 128, n0 = blockIdx.x * 128;
    const int wm   = (wid & 1) * 64, wn = (wid >> 1) * 32;
    const int gid  = lane >> 2, tig = lane & 3;

    A += (long)blockIdx.z * K;
    W += (long)blockIdx.z * K;

    const uint32_t sb = (uint32_t)__cvta_generic_to_shared(sm);

    const int arow = (lane & 7) + ((lane >> 3) & 1) * 8;
    const int acol = ((lane >> 4) & 1) * 16;
    const uint32_t a_off = (uint32_t)((wm + arow) * 144 + acol);
    const int brow = lane & 7;
    const int bcol = (lane >> 3) * 16;
    const uint32_t b_off = 18432u + (uint32_t)((wn + brow) * 144 + bcol);

    const int nk = K / 64;

#define LOADK(kq)                                                              \
    do {                                                                       \
        int _k = (kq);                                                         \
        if (_k < nk) {                                                         \
            uint32_t so = sb + (uint32_t)(_k % 3) * 36864u;                    \
            int ko = _k * 64;                                                  \
            _Pragma("unroll")                                                  \
            for (int j = 0; j < 4; j++) {                                      \
                int i = tid + j * 256;                                         \
                int row = i >> 3, c16 = i & 7;                                 \
                cp16(so + (uint32_t)(row * 144 + c16 * 16),                    \
                     A + (long)(m0 + row) * lda + ko + c16 * 8, true);         \
            }                                                                  \
            _Pragma("unroll")                                                  \
            for (int j = 0; j < 4; j++) {                                      \
                int i = tid + j * 256;                                         \
                int row = i >> 3, c16 = i & 7;                                 \
                bool ok = !NGUARD || (n0 + row) < Nt;                          \
                cp16(so + 18432u + (uint32_t)(row * 144 + c16 * 16),           \
                     W + (long)(ok ? (n0 + row) : 0) * ldb + ko + c16 * 8, ok);\
            }                                                                  \
        }                                                                      \
        asm volatile("cp.async.commit_group;\n");                              \
    } while (0)

    LOADK(0); LOADK(1);

    float acc[4][4][4];
#pragma unroll
    for (int i = 0; i < 4; i++)
#pragma unroll
        for (int j = 0; j < 4; j++)
#pragma unroll
            for (int q = 0; q < 4; q++) acc[i][j][q] = 0.f;

    for (int kt = 0; kt < nk; kt++) {
        asm volatile("cp.async.wait_group 1;\n" ::: "memory");
        __syncthreads();

        LOADK(kt + 2);

        const uint32_t bufb = sb + (uint32_t)(kt % 3) * 36864u;
        const uint32_t abase = bufb + a_off;
        const uint32_t bbase = bufb + b_off;

#pragma unroll
        for (int ksp = 0; ksp < 2; ksp++) {
            uint32_t bf[4][4];
#pragma unroll
            for (int ni = 0; ni < 4; ni++)
                ldsm4(bf[ni], bbase + (uint32_t)(ni * 8 * 144 + ksp * 64));
#pragma unroll
            for (int ks2 = 0; ks2 < 2; ks2++) {
                uint32_t af[4][4];
#pragma unroll
                for (int mi = 0; mi < 4; mi++)
                    ldsm4(af[mi], abase +
                          (uint32_t)(mi * 16 * 144 + (ksp * 2 + ks2) * 32));
#pragma unroll
                for (int mi = 0; mi < 4; mi++)
#pragma unroll
                    for (int ni = 0; ni < 4; ni++)
                        MMA_F16(acc[mi][ni],
                                af[mi][0], af[mi][1], af[mi][2], af[mi][3],
                                bf[ni][ks2 * 2], bf[ni][ks2 * 2 + 1]);
            }
        }
    }

    float* Cf  = (float*)Cv  + (OUTH ? 0 : (long)blockIdx.z * cz);
    __half* Ch = (__half*)Cv;

#pragma unroll
    for (int mi = 0; mi < 4; mi++) {
        const int r0 = m0 + wm + mi * 16 + gid;
        const int r1 = r0 + 8;
#pragma unroll
        for (int ni = 0; ni < 4; ni++) {
            const int cn = n0 + wn + ni * 8 + tig * 2;
            if (NGUARD && cn >= Nt) continue;
            float v0 = acc[mi][ni][0], v1 = acc[mi][ni][1];
            float v2 = acc[mi][ni][2], v3 = acc[mi][ni][3];
            if (ACT >= 1) {
                const float b0 = bias[cn], b1 = bias[cn + 1];
                v0 += b0; v1 += b1; v2 += b0; v3 += b1;
            }
            if (ACT == 2) {
                v0 = (v0 > 20.f) ? v0 : log1pf(__expf(v0));
                v1 = (v1 > 20.f) ? v1 : log1pf(__expf(v1));
                v2 = (v2 > 20.f) ? v2 : log1pf(__expf(v2));
                v3 = (v3 > 20.f) ? v3 : log1pf(__expf(v3));
            }
            if (OUTH) {
                *(__half2*)&Ch[(long)r0 * ldc + cn] = __floats2half2_rn(v0, v1);
                *(__half2*)&Ch[(long)r1 * ldc + cn] = __floats2half2_rn(v2, v3);
            } else {
                Cf[(long)r0 * ldc + cn]     = v0;
                Cf[(long)r0 * ldc + cn + 1] = v1;
                Cf[(long)r1 * ldc + cn]     = v2;
                Cf[(long)r1 * ldc + cn + 1] = v3;
            }
        }
    }
#undef LOADK
}

// ---------------- weight conversion to fp16 (split for ncu slotting) ---------
__global__ void round_wA_k(const float* __restrict__ w_in, const float* __restrict__ w_x,
                           const float* __restrict__ w_dt)
{
    const long i4 = ((long)blockIdx.x * 256 + threadIdx.x) * 4;
    if (i4 >= WOFF_OUT) return;
    const float* src;
    long off;
    if      (i4 < WOFF_X)   { src = w_in;  off = i4 - WOFF_IN;  }
    else if (i4 < WOFF_DT)  { src = w_x;   off = i4 - WOFF_X;   }
    else                    { src = w_dt;  off = i4 - WOFF_DT;  }
    float4 v = *(const float4*)(src + off);
    *(__half2*)&g_wr_h[i4]     = __floats2half2_rn(v.x, v.y);
    *(__half2*)&g_wr_h[i4 + 2] = __floats2half2_rn(v.z, v.w);
}

__global__ void round_wB_k(const float* __restrict__ w_out, const float* __restrict__ w_p)
{
    const long i4 = WOFF_OUT + ((long)blockIdx.x * 256 + threadIdx.x) * 4;
    if (i4 >= 7667712) return;
    const float* src;
    long off;
    if (i4 < WOFF_P) { src = w_out; off = i4 - WOFF_OUT; }
    else             { src = w_p;   off = i4 - WOFF_P;   }
    float4 v = *(const float4*)(src + off);
    *(__half2*)&g_wr_h[i4]     = __floats2half2_rn(v.x, v.y);
    *(__half2*)&g_wr_h[i4 + 2] = __floats2half2_rn(v.z, v.w);
}

// ---------------- transpose x: (B,d,L) -> (B,L,d) as fp16 --------------------
__global__ void transpose_f2h_k(const float* __restrict__ src)
{
    __shared__ float t[32][33];
    const int b  = blockIdx.z;
    const int r0 = blockIdx.y * 32, c0 = blockIdx.x * 32;   // r=d, c=l
    const float* s = src + (long)b * DMODEL * L_SEQ;
    __half* d = g_xt_h + (long)b * L_SEQ * DMODEL;
#pragma unroll
    for (int i = threadIdx.y; i < 32; i += 8)
        t[i][threadIdx.x] = s[(long)(r0 + i) * L_SEQ + c0 + threadIdx.x];
    __syncthreads();
#pragma unroll
    for (int i = threadIdx.y; i < 32; i += 8)
        d[(long)(c0 + i) * DMODEL + r0 + threadIdx.x] =
            __float2half_rn(t[threadIdx.x][i]);
}

// ---------------- transpose w_out (fp16): [m][d] 1024x2048 -> [d][m] ---------
__global__ void transpose_h_k()
{
    __shared__ __half t[32][34];
    const int r0 = blockIdx.y * 32, c0 = blockIdx.x * 32;   // r=m, c=d
    const __half* s = g_wr_h + WOFF_OUT;
#pragma unroll
    for (int i = threadIdx.y; i < 32; i += 8)
        t[i][threadIdx.x] = s[(long)(r0 + i) * DINNER + c0 + threadIdx.x];
    __syncthreads();
#pragma unroll
    for (int i = threadIdx.y; i < 32; i += 8)
        g_woutT[(long)(c0 + i) * DMODEL + r0 + threadIdx.x] = t[threadIdx.x][i];
}

// ---------------- final transpose: o2 [b][l][m] -> out [b][m][l] -------------
__global__ void transpose_ff_k(float* __restrict__ out)
{
    __shared__ float t[32][33];
    const int b  = blockIdx.z;
    const int m0 = blockIdx.x * 32, l0 = blockIdx.y * 32;
#pragma unroll
    for (int i = threadIdx.y; i < 32; i += 8)
        t[i][threadIdx.x] =
            g_o2[((long)b * L_SEQ + l0 + i) * DMODEL + m0 + threadIdx.x];
    __syncthreads();
#pragma unroll
    for (int i = threadIdx.y; i < 32; i += 8)
        out[((long)b * DMODEL + m0 + i) * L_SEQ + l0 + threadIdx.x] =
            t[threadIdx.x][i];
}

// ---------------- depthwise causal conv(4) + SiLU (fp16 in/out) --------------
__global__ void __launch_bounds__(256)
conv_silu_k(const float* __restrict__ cw, const float* __restrict__ cb)
{
    const long idx4 = (long)blockIdx.x * 256 + threadIdx.x;   // over MTOT*512
    const int  e4   = (int)(idx4 & 511) * 4;
    const long bl   = idx4 >> 9;
    const int  l    = (int)(bl & (L_SEQ - 1));
    const long brow = bl - l;
    const float4 w0 = *(const float4*)(cw + e4 * 4);
    const float4 w1 = *(const float4*)(cw + e4 * 4 + 4);
    const float4 w2 = *(const float4*)(cw + e4 * 4 + 8);
    const float4 w3 = *(const float4*)(cw + e4 * 4 + 12);
    float4 acc = *(const float4*)(cb + e4);
#pragma unroll
    for (int k = 0; k < 4; k++) {
        const int t = l - 3 + k;
        float x0 = 0.f, x1 = 0.f, x2 = 0.f, x3 = 0.f;
        if (t >= 0) {
            uint2 raw = *(const uint2*)&g_xz_h[(brow + t) * (2 * DINNER) + e4];
            float2 f01 = __half22float2(*(__half2*)&raw.x);
            float2 f23 = __half22float2(*(__half2*)&raw.y);
            x0 = f01.x; x1 = f01.y; x2 = f23.x; x3 = f23.y;
        }
        acc.x = fmaf(((const float*)&w0)[k], x0, acc.x);
        acc.y = fmaf(((const float*)&w1)[k], x1, acc.y);
        acc.z = fmaf(((const float*)&w2)[k], x2, acc.z);
        acc.w = fmaf(((const float*)&w3)[k], x3, acc.w);
    }
    acc.x = acc.x / (1.f + __expf(-acc.x));
    acc.y = acc.y / (1.f + __expf(-acc.y));
    acc.z = acc.z / (1.f + __expf(-acc.z));
    acc.w = acc.w / (1.f + __expf(-acc.w));
    *(__half2*)&g_uact_h[idx4 * 4]     = __floats2half2_rn(acc.x, acc.y);
    *(__half2*)&g_uact_h[idx4 * 4 + 2] = __floats2half2_rn(acc.z, acc.w);
}

// ---------------- split-K reduce for x_proj -> fp16 --------------------------
__global__ void reduce4_k()
{
    const long i = (long)blockIdx.x * 256 + threadIdx.x;
    const long S = (long)MTOT * 96;
    float v = g_part[i] + g_part[i + S] + g_part[i + 2 * S] + g_part[i + 3 * S];
    g_xdbl_h[i] = __float2half_rn(v);
}

// ---------------- selective scan: unroll-4, ping-pong sets, deferred shfl ----
// Two register sets alternate (load into one while computing from the other),
// eliminating the per-chunk register-copy MOVs. Arithmetic and reduction order
// identical to the rolled version.
__global__ void __launch_bounds__(256)
scan_k(const float* __restrict__ A_log, const float* __restrict__ Dp)
{
    const int b  = blockIdx.x >> 7;
    const int dg = blockIdx.x & 127;
    const int ci = threadIdx.x >> 4;
    const int n  = threadIdx.x & 15;
    const int d  = dg * 16 + ci;

    const float Av = -expf(A_log[d * DSTATE + n]);
    const float Dv = Dp[d];

    const long iA = ((long)b * L_SEQ) * DINNER + d;                  // delta/uact/yv
    const long iZ = ((long)b * L_SEQ) * (2 * DINNER) + DINNER + d;   // z (fp16)
    const long iX = ((long)b * L_SEQ) * 96;                          // xdbl (fp16)

    float dv[2][4], uv[2][4], zv[2][4], Bv[2][4], Cv[2][4];

#define LOAD4(s, L0)                                                       \
    if ((L0) < L_SEQ) {                                                    \
        _Pragma("unroll")                                                  \
        for (int j = 0; j < 4; j++) {                                      \
            const long ll = (long)(L0) + j;                                \
            dv[s][j] = g_delta[iA + ll * DINNER];                          \
            uv[s][j] = __half2float(g_uact_h[iA + ll * DINNER]);           \
            zv[s][j] = __half2float(g_xz_h[iZ + ll * 2 * DINNER]);         \
            Bv[s][j] = __half2float(g_xdbl_h[iX + ll * 96 + 64 + n]);      \
            Cv[s][j] = __half2float(g_xdbl_h[iX + ll * 96 + 80 + n]);      \
        }                                                                  \
    }

#define STEP4(s, L0) {                                                     \
        float pv[4];                                                       \
        _Pragma("unroll")                                                  \
        for (int j = 0; j < 4; j++) {                                      \
            float dA = __expf(dv[s][j] * Av);                              \
            h = fmaf(dA, h, dv[s][j] * Bv[s][j] * uv[s][j]);               \
            pv[j] = h * Cv[s][j];                                          \
        }                                                                  \
        _Pragma("unroll")                                                  \
        for (int st = 8; st >= 1; st >>= 1)                                \
            _Pragma("unroll")                                              \
            for (int j = 0; j < 4; j++)                                    \
                pv[j] += __shfl_xor_sync(0xffffffffu, pv[j], st, 16);      \
        if (n == 0) {                                                      \
            _Pragma("unroll")                                              \
            for (int j = 0; j < 4; j++) {                                  \
                float sil = zv[s][j] / (1.f + __expf(-zv[s][j]));          \
                g_yv_h[iA + ((long)(L0) + j) * DINNER] =                   \
                    __float2half_rn((pv[j] + uv[s][j] * Dv) * sil);        \
            }                                                              \
        }                                                                  \
    }

    float h = 0.f;
    LOAD4(0, 0);
    for (int l0 = 0; l0 < L_SEQ; l0 += 8) {
        LOAD4(1, l0 + 4);
        STEP4(0, l0);
        LOAD4(0, l0 + 8);
        STEP4(1, l0 + 4);
    }
#undef LOAD4
#undef STEP4
}

// ---------------- host launcher ----------------------------------------------
#define SMEM_T 110592   // 3 stages x 36864B

extern "C" void kernel_launch(void* const* d_in, const int* in_sizes, int n_in,
                              void* d_out, int out_size)
{
    (void)in_sizes; (void)n_in; (void)out_size;
    const float* x      = (const float*)d_in[0];
    const float* conv_w = (const float*)d_in[2];
    const float* conv_b = (const float*)d_in[3];
    const float* b_dt   = (const float*)d_in[6];
    const float* A_log  = (const float*)d_in[7];
    const float* Dp     = (const float*)d_in[8];
    const float* b_p    = (const float*)d_in[11];
    float* out = (float*)d_out;

    __half *xt, *xzh, *uact, *xdbl, *yv, *wr, *woutT, *wc;
    float *part, *delta, *o2;
    cudaGetSymbolAddress((void**)&xt,    g_xt_h);
    cudaGetSymbolAddress((void**)&xzh,   g_xz_h);
    cudaGetSymbolAddress((void**)&uact,  g_uact_h);
    cudaGetSymbolAddress((void**)&xdbl,  g_xdbl_h);
    cudaGetSymbolAddress((void**)&part,  g_part);
    cudaGetSymbolAddress((void**)&delta, g_delta);
    cudaGetSymbolAddress((void**)&yv,    g_yv_h);
    cudaGetSymbolAddress((void**)&o2,    g_o2);
    cudaGetSymbolAddress((void**)&wr,    g_wr_h);
    cudaGetSymbolAddress((void**)&woutT, g_woutT);
    cudaGetSymbolAddress((void**)&wc,    g_wc);

    cudaFuncSetAttribute(hgemm<0,false,false>, cudaFuncAttributeMaxDynamicSharedMemorySize, SMEM_T);
    cudaFuncSetAttribute(hgemm<0,true, false>, cudaFuncAttributeMaxDynamicSharedMemorySize, SMEM_T);
    cudaFuncSetAttribute(hgemm<2,false,false>, cudaFuncAttributeMaxDynamicSharedMemorySize, SMEM_T);
    cudaFuncSetAttribute(hgemm<0,false,true >, cudaFuncAttributeMaxDynamicSharedMemorySize, SMEM_T);
    cudaFuncSetAttribute(hgemm<1,false,false>, cudaFuncAttributeMaxDynamicSharedMemorySize, SMEM_T);

    // launches 1-3 (slot 4 = in_proj stays the ncu-captured launch)
    round_wA_k<<<(WOFF_OUT / 4 + 255) / 256, 256>>>(
        (const float*)d_in[1], (const float*)d_in[4], (const float*)d_in[5]);
    round_wB_k<<<((7667712 - WOFF_OUT) / 4 + 255) / 256, 256>>>(
        (const float*)d_in[9], (const float*)d_in[10]);
    transpose_f2h_k<<<dim3(L_SEQ / 32, DMODEL / 32, B_SZ), dim3(32, 8)>>>(x);

    // 4) in_proj: xz = xt @ w_in^T   (fp16 out)  K=1024   [ncu slot]
    hgemm<0,false,true><<<dim3(32, 64, 1), 256, SMEM_T>>>(
        xt, wr + WOFF_IN, nullptr, xzh, 1024, DMODEL, DMODEL, 2 * DINNER, 0, 0);

    // 5-6) fused tail-projection prep: woutT = w_out^T; wc = w_p @ w_out
    transpose_h_k<<<dim3(DINNER / 32, DMODEL / 32), dim3(32, 8)>>>();
    hgemm<0,false,true><<<dim3(16, 8, 1), 256, SMEM_T>>>(
        wr + WOFF_P, woutT, nullptr, wc, 1024, DMODEL, DMODEL, DINNER, 0, 0);

    // 7) conv + silu -> uact (fp16)
    conv_silu_k<<<((long)MTOT * 512) / 256, 256>>>(conv_w, conv_b);

    // 8) x_proj split-K x4 (fp32 partials) + reduce -> xdbl fp16
    hgemm<0,true,false><<<dim3(1, 64, 4), 256, SMEM_T>>>(
        uact, wr + WOFF_X, nullptr, part, 512, DINNER, DINNER, 96, 96,
        (long)MTOT * 96);
    reduce4_k<<<((long)MTOT * 96) / 256, 256>>>();

    // 9) delta = softplus(xdbl[:, :64] @ w_dt^T + b_dt)  (fp32 out)  K=64
    hgemm<2,false,false><<<dim3(16, 64, 1), 256, SMEM_T>>>(
        xdbl, wr + WOFF_DT, b_dt, delta, 64, 96, 64, DINNER, 0, 0);

    // 10) selective scan -> yv (fp16)
    scan_k<<<B_SZ * (DINNER / 16), 256>>>(A_log, Dp);

    // 11) fused out_proj+proj: o2 = yv @ wc^T + b_p  (fp32 out)  K=2048
    hgemm<1,false,false><<<dim3(8, 64, 1), 256, SMEM_T>>>(
        yv, wc, b_p, o2, 2048, DINNER, DINNER, DMODEL, 0, 0);

    // 12) transpose to (B, d_model, L)
    transpose_ff_k<<<dim3(DMODEL / 32, L_SEQ / 32, B_SZ), dim3(32, 8)>>>(out);
}

// round 15
// speedup vs baseline: 1.2916x; 1.2916x over previous
#include <cuda_runtime.h>
#include <cuda_fp16.h>
#include <math.h>
#include <stdint.h>

#define B_SZ   4
#define L_SEQ  2048
#define DMODEL 1024
#define DINNER 2048
#define DSTATE 16
#define MTOT   (B_SZ * L_SEQ)   // 8192

// ---------------- scratch ----------------------------------------------------
__device__ __half g_xt_h  [(size_t)MTOT * DMODEL];      // x^T as fp16
__device__ __half g_xz_h  [(size_t)MTOT * 2 * DINNER];  // in_proj out (u|z) fp16
__device__ __half g_uact_h[(size_t)MTOT * DINNER];      // conv+silu, fp16
__device__ __half g_xdbl_h[(size_t)MTOT * 96];          // x_proj out, fp16
__device__ float  g_part  [(size_t)4 * MTOT * 96];      // split-K partials
__device__ float  g_delta [(size_t)MTOT * DINNER];      // softplus(dt)
__device__ __half g_yv_h  [(size_t)MTOT * DINNER];      // scan out, fp16
__device__ float  g_o2    [(size_t)MTOT * DMODEL];
__device__ __half g_wr_h  [7667712];                    // all weights, fp16
__device__ __half g_woutT [(size_t)DINNER * DMODEL];    // w_out^T  [d][m]
__device__ __half g_wc    [(size_t)DMODEL * DINNER];    // w_p@w_out [e][d]

#define WOFF_IN  0
#define WOFF_X   4194304
#define WOFF_DT  4390912
#define WOFF_OUT 4521984
#define WOFF_P   6619136

__device__ __forceinline__ void cp16(uint32_t dst, const void* src, bool pred) {
    int sz = pred ? 16 : 0;
    asm volatile("cp.async.cg.shared.global [%0], [%1], 16, %2;\n"
                 :: "r"(dst), "l"(src), "r"(sz));
}

__device__ __forceinline__ void ldsm4(uint32_t* r, uint32_t addr) {
    asm volatile("ldmatrix.sync.aligned.m8n8.x4.shared.b16 {%0,%1,%2,%3}, [%4];"
                 : "=r"(r[0]), "=r"(r[1]), "=r"(r[2]), "=r"(r[3]) : "r"(addr));
}

#define MMA_F16(c, a0, a1, a2, a3, b0, b1)                            \
    asm volatile(                                                     \
        "mma.sync.aligned.m16n8k16.row.col.f32.f16.f16.f32 "          \
        "{%0,%1,%2,%3}, {%4,%5,%6,%7}, {%8,%9}, {%0,%1,%2,%3};\n"     \
        : "+f"(c[0]), "+f"(c[1]), "+f"(c[2]), "+f"(c[3])              \
        : "r"(a0), "r"(a1), "r"(a2), "r"(a3), "r"(b0), "r"(b1))

// ---------------- fp16 GEMM (fp32 accum), 64-k chunks, 3 stages --------------
// A half [M, lda]; W half [N, ldb]; C[m,n] = sum_k A[m,k] W[n,k] (+bias)(+act).
// ACT: 0 none, 1 +bias, 2 +bias+softplus.  OUTH: write half (else float).
template<int ACT, bool NGUARD, bool OUTH>
__global__ void __launch_bounds__(256, 2)
hgemm(const __half* __restrict__ A, const __half* __restrict__ W,
      const float* __restrict__ bias, void* __restrict__ Cv,
      int K, int lda, int ldb, int ldc, int Nt, long cz)
{
    extern __shared__ float sm[];
    const int tid  = threadIdx.x;
    const int wid  = tid >> 5, lane = tid & 31;
    const int m0   = blockIdx.y * 128, n0 = blockIdx.x * 128;
    const int wm   = (wid & 1) * 64, wn = (wid >> 1) * 32;
    const int gid  = lane >> 2, tig = lane & 3;

    A += (long)blockIdx.z * K;
    W += (long)blockIdx.z * K;

    const uint32_t sb = (uint32_t)__cvta_generic_to_shared(sm);

    const int arow = (lane & 7) + ((lane >> 3) & 1) * 8;
    const int acol = ((lane >> 4) & 1) * 16;
    const uint32_t a_off = (uint32_t)((wm + arow) * 144 + acol);
    const int brow = lane & 7;
    const int bcol = (lane >> 3) * 16;
    const uint32_t b_off = 18432u + (uint32_t)((wn + brow) * 144 + bcol);

    const int nk = K / 64;

#define LOADK(kq)                                                              \
    do {                                                                       \
        int _k = (kq);                                                         \
        if (_k < nk) {                                                         \
            uint32_t so = sb + (uint32_t)(_k % 3) * 36864u;                    \
            int ko = _k * 64;                                                  \
            _Pragma("unroll")                                                  \
            for (int j = 0; j < 4; j++) {                                      \
                int i = tid + j * 256;                                         \
                int row = i >> 3, c16 = i & 7;                                 \
                cp16(so + (uint32_t)(row * 144 + c16 * 16),                    \
                     A + (long)(m0 + row) * lda + ko + c16 * 8, true);         \
            }                                                                  \
            _Pragma("unroll")                                                  \
            for (int j = 0; j < 4; j++) {                                      \
                int i = tid + j * 256;                                         \
                int row = i >> 3, c16 = i & 7;                                 \
                bool ok = !NGUARD || (n0 + row) < Nt;                          \
                cp16(so + 18432u + (uint32_t)(row * 144 + c16 * 16),           \
                     W + (long)(ok ? (n0 + row) : 0) * ldb + ko + c16 * 8, ok);\
            }                                                                  \
        }                                                                      \
        asm volatile("cp.async.commit_group;\n");                              \
    } while (0)

    LOADK(0); LOADK(1);

    float acc[4][4][4];
#pragma unroll
    for (int i = 0; i < 4; i++)
#pragma unroll
        for (int j = 0; j < 4; j++)
#pragma unroll
            for (int q = 0; q < 4; q++) acc[i][j][q] = 0.f;

    for (int kt = 0; kt < nk; kt++) {
        asm volatile("cp.async.wait_group 1;\n" ::: "memory");
        __syncthreads();

        LOADK(kt + 2);

        const uint32_t bufb = sb + (uint32_t)(kt % 3) * 36864u;
        const uint32_t abase = bufb + a_off;
        const uint32_t bbase = bufb + b_off;

#pragma unroll
        for (int ksp = 0; ksp < 2; ksp++) {
            uint32_t bf[4][4];
#pragma unroll
            for (int ni = 0; ni < 4; ni++)
                ldsm4(bf[ni], bbase + (uint32_t)(ni * 8 * 144 + ksp * 64));
#pragma unroll
            for (int ks2 = 0; ks2 < 2; ks2++) {
                uint32_t af[4][4];
#pragma unroll
                for (int mi = 0; mi < 4; mi++)
                    ldsm4(af[mi], abase +
                          (uint32_t)(mi * 16 * 144 + (ksp * 2 + ks2) * 32));
#pragma unroll
                for (int mi = 0; mi < 4; mi++)
#pragma unroll
                    for (int ni = 0; ni < 4; ni++)
                        MMA_F16(acc[mi][ni],
                                af[mi][0], af[mi][1], af[mi][2], af[mi][3],
                                bf[ni][ks2 * 2], bf[ni][ks2 * 2 + 1]);
            }
        }
    }

    float* Cf  = (float*)Cv  + (OUTH ? 0 : (long)blockIdx.z * cz);
    __half* Ch = (__half*)Cv;

#pragma unroll
    for (int mi = 0; mi < 4; mi++) {
        const int r0 = m0 + wm + mi * 16 + gid;
        const int r1 = r0 + 8;
#pragma unroll
        for (int ni = 0; ni < 4; ni++) {
            const int cn = n0 + wn + ni * 8 + tig * 2;
            if (NGUARD && cn >= Nt) continue;
            float v0 = acc[mi][ni][0], v1 = acc[mi][ni][1];
            float v2 = acc[mi][ni][2], v3 = acc[mi][ni][3];
            if (ACT >= 1) {
                const float b0 = bias[cn], b1 = bias[cn + 1];
                v0 += b0; v1 += b1; v2 += b0; v3 += b1;
            }
            if (ACT == 2) {
                v0 = (v0 > 20.f) ? v0 : log1pf(__expf(v0));
                v1 = (v1 > 20.f) ? v1 : log1pf(__expf(v1));
                v2 = (v2 > 20.f) ? v2 : log1pf(__expf(v2));
                v3 = (v3 > 20.f) ? v3 : log1pf(__expf(v3));
            }
            if (OUTH) {
                *(__half2*)&Ch[(long)r0 * ldc + cn] = __floats2half2_rn(v0, v1);
                *(__half2*)&Ch[(long)r1 * ldc + cn] = __floats2half2_rn(v2, v3);
            } else {
                Cf[(long)r0 * ldc + cn]     = v0;
                Cf[(long)r0 * ldc + cn + 1] = v1;
                Cf[(long)r1 * ldc + cn]     = v2;
                Cf[(long)r1 * ldc + cn + 1] = v3;
            }
        }
    }
#undef LOADK
}

// ---------------- weight conversion to fp16 (split for ncu slotting) ---------
__global__ void round_wA_k(const float* __restrict__ w_in, const float* __restrict__ w_x,
                           const float* __restrict__ w_dt)
{
    const long i4 = ((long)blockIdx.x * 256 + threadIdx.x) * 4;
    if (i4 >= WOFF_OUT) return;
    const float* src;
    long off;
    if      (i4 < WOFF_X)   { src = w_in;  off = i4 - WOFF_IN;  }
    else if (i4 < WOFF_DT)  { src = w_x;   off = i4 - WOFF_X;   }
    else                    { src = w_dt;  off = i4 - WOFF_DT;  }
    float4 v = *(const float4*)(src + off);
    *(__half2*)&g_wr_h[i4]     = __floats2half2_rn(v.x, v.y);
    *(__half2*)&g_wr_h[i4 + 2] = __floats2half2_rn(v.z, v.w);
}

__global__ void round_wB_k(const float* __restrict__ w_out, const float* __restrict__ w_p)
{
    const long i4 = WOFF_OUT + ((long)blockIdx.x * 256 + threadIdx.x) * 4;
    if (i4 >= 7667712) return;
    const float* src;
    long off;
    if (i4 < WOFF_P) { src = w_out; off = i4 - WOFF_OUT; }
    else             { src = w_p;   off = i4 - WOFF_P;   }
    float4 v = *(const float4*)(src + off);
    *(__half2*)&g_wr_h[i4]     = __floats2half2_rn(v.x, v.y);
    *(__half2*)&g_wr_h[i4 + 2] = __floats2half2_rn(v.z, v.w);
}

// ---------------- transpose x: (B,d,L) -> (B,L,d) as fp16 --------------------
__global__ void transpose_f2h_k(const float* __restrict__ src)
{
    __shared__ float t[32][33];
    const int b  = blockIdx.z;
    const int r0 = blockIdx.y * 32, c0 = blockIdx.x * 32;   // r=d, c=l
    const float* s = src + (long)b * DMODEL * L_SEQ;
    __half* d = g_xt_h + (long)b * L_SEQ * DMODEL;
#pragma unroll
    for (int i = threadIdx.y; i < 32; i += 8)
        t[i][threadIdx.x] = s[(long)(r0 + i) * L_SEQ + c0 + threadIdx.x];
    __syncthreads();
#pragma unroll
    for (int i = threadIdx.y; i < 32; i += 8)
        d[(long)(c0 + i) * DMODEL + r0 + threadIdx.x] =
            __float2half_rn(t[threadIdx.x][i]);
}

// ---------------- transpose w_out (fp16): [m][d] 1024x2048 -> [d][m] ---------
__global__ void transpose_h_k()
{
    __shared__ __half t[32][34];
    const int r0 = blockIdx.y * 32, c0 = blockIdx.x * 32;   // r=m, c=d
    const __half* s = g_wr_h + WOFF_OUT;
#pragma unroll
    for (int i = threadIdx.y; i < 32; i += 8)
        t[i][threadIdx.x] = s[(long)(r0 + i) * DINNER + c0 + threadIdx.x];
    __syncthreads();
#pragma unroll
    for (int i = threadIdx.y; i < 32; i += 8)
        g_woutT[(long)(c0 + i) * DMODEL + r0 + threadIdx.x] = t[threadIdx.x][i];
}

// ---------------- final transpose: o2 [b][l][m] -> out [b][m][l] -------------
__global__ void transpose_ff_k(float* __restrict__ out)
{
    __shared__ float t[32][33];
    const int b  = blockIdx.z;
    const int m0 = blockIdx.x * 32, l0 = blockIdx.y * 32;
#pragma unroll
    for (int i = threadIdx.y; i < 32; i += 8)
        t[i][threadIdx.x] =
            g_o2[((long)b * L_SEQ + l0 + i) * DMODEL + m0 + threadIdx.x];
    __syncthreads();
#pragma unroll
    for (int i = threadIdx.y; i < 32; i += 8)
        out[((long)b * DMODEL + m0 + i) * L_SEQ + l0 + threadIdx.x] =
            t[threadIdx.x][i];
}

// ---------------- depthwise causal conv(4) + SiLU (fp16 in/out) --------------
__global__ void __launch_bounds__(256)
conv_silu_k(const float* __restrict__ cw, const float* __restrict__ cb)
{
    const long idx4 = (long)blockIdx.x * 256 + threadIdx.x;   // over MTOT*512
    const int  e4   = (int)(idx4 & 511) * 4;
    const long bl   = idx4 >> 9;
    const int  l    = (int)(bl & (L_SEQ - 1));
    const long brow = bl - l;
    const float4 w0 = *(const float4*)(cw + e4 * 4);
    const float4 w1 = *(const float4*)(cw + e4 * 4 + 4);
    const float4 w2 = *(const float4*)(cw + e4 * 4 + 8);
    const float4 w3 = *(const float4*)(cw + e4 * 4 + 12);
    float4 acc = *(const float4*)(cb + e4);
#pragma unroll
    for (int k = 0; k < 4; k++) {
        const int t = l - 3 + k;
        float x0 = 0.f, x1 = 0.f, x2 = 0.f, x3 = 0.f;
        if (t >= 0) {
            uint2 raw = *(const uint2*)&g_xz_h[(brow + t) * (2 * DINNER) + e4];
            float2 f01 = __half22float2(*(__half2*)&raw.x);
            float2 f23 = __half22float2(*(__half2*)&raw.y);
            x0 = f01.x; x1 = f01.y; x2 = f23.x; x3 = f23.y;
        }
        acc.x = fmaf(((const float*)&w0)[k], x0, acc.x);
        acc.y = fmaf(((const float*)&w1)[k], x1, acc.y);
        acc.z = fmaf(((const float*)&w2)[k], x2, acc.z);
        acc.w = fmaf(((const float*)&w3)[k], x3, acc.w);
    }
    acc.x = acc.x / (1.f + __expf(-acc.x));
    acc.y = acc.y / (1.f + __expf(-acc.y));
    acc.z = acc.z / (1.f + __expf(-acc.z));
    acc.w = acc.w / (1.f + __expf(-acc.w));
    *(__half2*)&g_uact_h[idx4 * 4]     = __floats2half2_rn(acc.x, acc.y);
    *(__half2*)&g_uact_h[idx4 * 4 + 2] = __floats2half2_rn(acc.z, acc.w);
}

// ---------------- split-K reduce for x_proj -> fp16 --------------------------
__global__ void reduce4_k()
{
    const long i = (long)blockIdx.x * 256 + threadIdx.x;
    const long S = (long)MTOT * 96;
    float v = g_part[i] + g_part[i + S] + g_part[i + 2 * S] + g_part[i + 3 * S];
    g_xdbl_h[i] = __float2half_rn(v);
}

// ---------------- selective scan: R12 structure (unroll-4, deferred shfl) ----
// Exact scheduling that measured fast in R12; only the z load is fp16 now.
__global__ void __launch_bounds__(256)
scan_k(const float* __restrict__ A_log, const float* __restrict__ Dp)
{
    const int b  = blockIdx.x >> 7;
    const int dg = blockIdx.x & 127;
    const int ci = threadIdx.x >> 4;
    const int n  = threadIdx.x & 15;
    const int d  = dg * 16 + ci;

    const float Av = -expf(A_log[d * DSTATE + n]);
    const float Dv = Dp[d];

    long i2048 = ((long)b * L_SEQ) * DINNER + d;
    long i4096 = ((long)b * L_SEQ) * (2 * DINNER) + DINNER + d;
    long i96   = ((long)b * L_SEQ) * 96;

    float dv[4], uv[4], zv[4], Bv[4], Cv[4];
#pragma unroll
    for (int j = 0; j < 4; j++) {
        dv[j] = g_delta[i2048 + (long)j * DINNER];
        uv[j] = __half2float(g_uact_h[i2048 + (long)j * DINNER]);
        zv[j] = __half2float(g_xz_h[i4096 + (long)j * 2 * DINNER]);
        Bv[j] = __half2float(g_xdbl_h[i96 + j * 96 + 64 + n]);
        Cv[j] = __half2float(g_xdbl_h[i96 + j * 96 + 80 + n]);
    }

    float h = 0.f;
    for (int l0 = 0; l0 < L_SEQ; l0 += 4) {
        float dvN[4], uvN[4], zvN[4], BvN[4], CvN[4];
        if (l0 + 4 < L_SEQ) {
            const long a = i2048 + 4 * DINNER;
            const long zb = i4096 + 8 * DINNER;
            const long c = i96 + 4 * 96;
#pragma unroll
            for (int j = 0; j < 4; j++) {
                dvN[j] = g_delta[a + (long)j * DINNER];
                uvN[j] = __half2float(g_uact_h[a + (long)j * DINNER]);
                zvN[j] = __half2float(g_xz_h[zb + (long)j * 2 * DINNER]);
                BvN[j] = __half2float(g_xdbl_h[c + j * 96 + 64 + n]);
                CvN[j] = __half2float(g_xdbl_h[c + j * 96 + 80 + n]);
            }
        } else {
#pragma unroll
            for (int j = 0; j < 4; j++) {
                dvN[j] = 0.f; uvN[j] = 0.f; zvN[j] = 0.f;
                BvN[j] = 0.f; CvN[j] = 0.f;
            }
        }

        float pv[4];
#pragma unroll
        for (int j = 0; j < 4; j++) {
            float dA = __expf(dv[j] * Av);
            h = fmaf(dA, h, dv[j] * Bv[j] * uv[j]);
            pv[j] = h * Cv[j];
        }
#pragma unroll
        for (int st = 8; st >= 1; st >>= 1)
#pragma unroll
            for (int j = 0; j < 4; j++)
                pv[j] += __shfl_xor_sync(0xffffffffu, pv[j], st, 16);
        if (n == 0) {
#pragma unroll
            for (int j = 0; j < 4; j++) {
                float sil = zv[j] / (1.f + __expf(-zv[j]));
                g_yv_h[i2048 + (long)j * DINNER] =
                    __float2half_rn((pv[j] + uv[j] * Dv) * sil);
            }
        }

#pragma unroll
        for (int j = 0; j < 4; j++) {
            dv[j] = dvN[j]; uv[j] = uvN[j]; zv[j] = zvN[j];
            Bv[j] = BvN[j]; Cv[j] = CvN[j];
        }
        i2048 += 4 * DINNER; i4096 += 8 * DINNER; i96 += 4 * 96;
    }
}

// ---------------- host launcher ----------------------------------------------
#define SMEM_T 110592   // 3 stages x 36864B

extern "C" void kernel_launch(void* const* d_in, const int* in_sizes, int n_in,
                              void* d_out, int out_size)
{
    (void)in_sizes; (void)n_in; (void)out_size;
    const float* x      = (const float*)d_in[0];
    const float* conv_w = (const float*)d_in[2];
    const float* conv_b = (const float*)d_in[3];
    const float* b_dt   = (const float*)d_in[6];
    const float* A_log  = (const float*)d_in[7];
    const float* Dp     = (const float*)d_in[8];
    const float* b_p    = (const float*)d_in[11];
    float* out = (float*)d_out;

    __half *xt, *xzh, *uact, *xdbl, *yv, *wr, *woutT, *wc;
    float *part, *delta, *o2;
    cudaGetSymbolAddress((void**)&xt,    g_xt_h);
    cudaGetSymbolAddress((void**)&xzh,   g_xz_h);
    cudaGetSymbolAddress((void**)&uact,  g_uact_h);
    cudaGetSymbolAddress((void**)&xdbl,  g_xdbl_h);
    cudaGetSymbolAddress((void**)&part,  g_part);
    cudaGetSymbolAddress((void**)&delta, g_delta);
    cudaGetSymbolAddress((void**)&yv,    g_yv_h);
    cudaGetSymbolAddress((void**)&o2,    g_o2);
    cudaGetSymbolAddress((void**)&wr,    g_wr_h);
    cudaGetSymbolAddress((void**)&woutT, g_woutT);
    cudaGetSymbolAddress((void**)&wc,    g_wc);

    cudaFuncSetAttribute(hgemm<0,false,false>, cudaFuncAttributeMaxDynamicSharedMemorySize, SMEM_T);
    cudaFuncSetAttribute(hgemm<0,true, false>, cudaFuncAttributeMaxDynamicSharedMemorySize, SMEM_T);
    cudaFuncSetAttribute(hgemm<2,false,false>, cudaFuncAttributeMaxDynamicSharedMemorySize, SMEM_T);
    cudaFuncSetAttribute(hgemm<0,false,true >, cudaFuncAttributeMaxDynamicSharedMemorySize, SMEM_T);
    cudaFuncSetAttribute(hgemm<1,false,false>, cudaFuncAttributeMaxDynamicSharedMemorySize, SMEM_T);

    // launches 1-3 (slot 4 = in_proj stays the ncu-captured launch)
    round_wA_k<<<(WOFF_OUT / 4 + 255) / 256, 256>>>(
        (const float*)d_in[1], (const float*)d_in[4], (const float*)d_in[5]);
    round_wB_k<<<((7667712 - WOFF_OUT) / 4 + 255) / 256, 256>>>(
        (const float*)d_in[9], (const float*)d_in[10]);
    transpose_f2h_k<<<dim3(L_SEQ / 32, DMODEL / 32, B_SZ), dim3(32, 8)>>>(x);

    // 4) in_proj: xz = xt @ w_in^T   (fp16 out)  K=1024   [ncu slot]
    hgemm<0,false,true><<<dim3(32, 64, 1), 256, SMEM_T>>>(
        xt, wr + WOFF_IN, nullptr, xzh, 1024, DMODEL, DMODEL, 2 * DINNER, 0, 0);

    // 5-6) fused tail-projection prep: woutT = w_out^T; wc = w_p @ w_out
    transpose_h_k<<<dim3(DINNER / 32, DMODEL / 32), dim3(32, 8)>>>();
    hgemm<0,false,true><<<dim3(16, 8, 1), 256, SMEM_T>>>(
        wr + WOFF_P, woutT, nullptr, wc, 1024, DMODEL, DMODEL, DINNER, 0, 0);

    // 7) conv + silu -> uact (fp16)
    conv_silu_k<<<((long)MTOT * 512) / 256, 256>>>(conv_w, conv_b);

    // 8) x_proj split-K x4 (fp32 partials) + reduce -> xdbl fp16
    hgemm<0,true,false><<<dim3(1, 64, 4), 256, SMEM_T>>>(
        uact, wr + WOFF_X, nullptr, part, 512, DINNER, DINNER, 96, 96,
        (long)MTOT * 96);
    reduce4_k<<<((long)MTOT * 96) / 256, 256>>>();

    // 9) delta = softplus(xdbl[:, :64] @ w_dt^T + b_dt)  (fp32 out)  K=64
    hgemm<2,false,false><<<dim3(16, 64, 1), 256, SMEM_T>>>(
        xdbl, wr + WOFF_DT, b_dt, delta, 64, 96, 64, DINNER, 0, 0);

    // 10) selective scan -> yv (fp16)
    scan_k<<<B_SZ * (DINNER / 16), 256>>>(A_log, Dp);

    // 11) fused out_proj+proj: o2 = yv @ wc^T + b_p  (fp32 out)  K=2048
    hgemm<1,false,false><<<dim3(8, 64, 1), 256, SMEM_T>>>(
        yv, wc, b_p, o2, 2048, DINNER, DINNER, DMODEL, 0, 0);

    // 12) transpose to (B, d_model, L)
    transpose_ff_k<<<dim3(DMODEL / 32, L_SEQ / 32, B_SZ), dim3(32, 8)>>>(out);
}